// round 4
// baseline (speedup 1.0000x reference)
#include <cuda_runtime.h>
#include <math.h>

#define BB 64
#define NN 512
#define DD 128
#define UU 64
#define NB 64
#define NSTEPS (NN/NB)

// Scratch (allocation-free rule: __device__ globals)
__device__ float g_M[BB*NN*NN];   // 67 MB: Cholesky workspace (copy of A)
__device__ float g_chi[BB*NN];

__device__ __forceinline__ float tshrink(float x) { return x - tanhf(x); }

// ---------------------------------------------------------------------------
// chi = MLP(node_feats): 32 rows per block, 256 threads
// ---------------------------------------------------------------------------
__global__ void chi_kernel(const float* __restrict__ nf,
                           const float* __restrict__ W1, const float* __restrict__ b1,
                           const float* __restrict__ W2, const float* __restrict__ b2,
                           const float* __restrict__ W3, const float* __restrict__ b3)
{
    __shared__ float xs[32][DD];
    __shared__ float h1[32][UU];
    __shared__ float h2[32][UU];
    const int row0 = blockIdx.x * 32;
    const int tid  = threadIdx.x;

    for (int idx = tid; idx < 32*DD; idx += 256)
        xs[idx/DD][idx%DD] = nf[(size_t)row0*DD + idx];
    __syncthreads();

    for (int o = tid; o < 32*UU; o += 256) {
        int r = o / UU, u = o % UU;
        float acc = b1[u];
        #pragma unroll 8
        for (int d = 0; d < DD; d++) acc += xs[r][d] * W1[d*UU + u];
        h1[r][u] = tshrink(acc);
    }
    __syncthreads();

    for (int o = tid; o < 32*UU; o += 256) {
        int r = o / UU, u = o % UU;
        float acc = b2[u];
        #pragma unroll 8
        for (int d = 0; d < UU; d++) acc += h1[r][d] * W2[d*UU + u];
        h2[r][u] = tshrink(acc);
    }
    __syncthreads();

    if (tid < 32) {
        float acc = b3[0];
        #pragma unroll 8
        for (int d = 0; d < UU; d++) acc += h2[tid][d] * W3[d];
        g_chi[row0 + tid] = tshrink(acc);
    }
}

// ---------------------------------------------------------------------------
// Build A (B,N,N): 32x32 tile per block, write to output AND scratch
// ---------------------------------------------------------------------------
__global__ void buildA_kernel(const float* __restrict__ pos,
                              const int*   __restrict__ ntype,
                              const float* __restrict__ hardness,
                              const float* __restrict__ sigma,
                              float* __restrict__ outA)
{
    __shared__ float pix[32], piy[32], piz[32];
    __shared__ float pjx[32], pjy[32], pjz[32];
    __shared__ float si[32], sj[32], hi[32];

    const int b  = blockIdx.z;
    const int it = blockIdx.y, jt = blockIdx.x;
    const int tid = threadIdx.x;
    const float kC = 14.399645351950548f;

    if (tid < 32) {
        int gi = it*32 + tid;
        const float* p = pos + ((size_t)b*NN + gi)*3;
        pix[tid]=p[0]; piy[tid]=p[1]; piz[tid]=p[2];
        int t = ntype[b*NN + gi];
        si[tid] = sigma[t]; hi[tid] = hardness[t];
    } else if (tid < 64) {
        int l = tid - 32;
        int gj = jt*32 + l;
        const float* p = pos + ((size_t)b*NN + gj)*3;
        pjx[l]=p[0]; pjy[l]=p[1]; pjz[l]=p[2];
        sj[l] = sigma[ntype[b*NN + gj]];
    }
    __syncthreads();

    float* Ab = outA + (size_t)b*NN*NN;
    float* Mb = g_M  + (size_t)b*NN*NN;

    for (int e = tid; e < 32*32; e += 256) {
        int li = e >> 5, lj = e & 31;
        int i = it*32 + li, j = jt*32 + lj;
        float dx = pix[li]-pjx[lj], dy = piy[li]-pjy[lj], dz = piz[li]-pjz[lj];
        float dist = sqrtf(dx*dx + dy*dy + dz*dz) + 1e-8f;
        float g2 = si[li]*si[li] + sj[lj]*sj[lj];
        float arg = dist * rsqrtf(2.0f * g2);
        float a = kC * erff(arg) / dist;
        if (i == j) {
            // hardness + k / (sqrt(pi) * sqrt(2) * sigma)
            a += hi[li] + kC / (1.7724538509055159f * 1.4142135623730951f * si[li]);
        }
        size_t off = (size_t)i*NN + j;
        Ab[off] = a;
        Mb[off] = a;
    }
}

// ---------------------------------------------------------------------------
// Blocked Cholesky (NB=64), one step per set of launches. L stored in lower
// triangle of g_M in-place. Upper triangle becomes garbage (never read).
// ---------------------------------------------------------------------------
__global__ void potrf_kernel(int k0)
{
    __shared__ float S[NB][NB+1];
    const int b = blockIdx.x;
    float* Mb = g_M + (size_t)b*NN*NN;
    const int tid = threadIdx.x;  // 256

    for (int idx = tid; idx < NB*NB; idx += 256)
        S[idx>>6][idx&63] = Mb[(size_t)(k0 + (idx>>6))*NN + k0 + (idx&63)];
    __syncthreads();

    for (int j = 0; j < NB; j++) {
        float invd = rsqrtf(S[j][j]);   // stable since last sync
        __syncthreads();
        if (tid >= j && tid < NB) S[tid][j] *= invd;
        __syncthreads();
        for (int idx = tid; idx < NB*NB; idx += 256) {
            int i = idx >> 6, c = idx & 63;
            if (c > j && i >= c) S[i][c] -= S[i][j] * S[c][j];
        }
        __syncthreads();
    }

    for (int idx = tid; idx < NB*NB; idx += 256)
        Mb[(size_t)(k0 + (idx>>6))*NN + k0 + (idx&63)] = S[idx>>6][idx&63];
}

// L21 = A21 * L11^{-T}: one row per thread, row in registers, fully unrolled
__global__ void trsm_kernel(int k0)
{
    __shared__ float Ls[NB][NB+1];
    __shared__ float sinv[NB];
    const int b = blockIdx.y;
    float* Mb = g_M + (size_t)b*NN*NN;
    const int tid = threadIdx.x;  // 128

    for (int idx = tid; idx < NB*NB; idx += 128)
        Ls[idx>>6][idx&63] = Mb[(size_t)(k0 + (idx>>6))*NN + k0 + (idx&63)];
    __syncthreads();
    if (tid < NB) sinv[tid] = 1.0f / Ls[tid][tid];
    __syncthreads();

    int row = k0 + NB + blockIdx.x*128 + tid;
    if (row < NN) {
        float a[NB];
        float4* src = (float4*)(Mb + (size_t)row*NN + k0);
        #pragma unroll
        for (int q = 0; q < NB/4; q++) {
            float4 v = src[q];
            a[4*q]=v.x; a[4*q+1]=v.y; a[4*q+2]=v.z; a[4*q+3]=v.w;
        }
        #pragma unroll
        for (int c = 0; c < NB; c++) {
            float acc = a[c];
            #pragma unroll
            for (int p = 0; p < c; p++) acc -= a[p] * Ls[c][p];
            a[c] = acc * sinv[c];
        }
        #pragma unroll
        for (int q = 0; q < NB/4; q++)
            src[q] = make_float4(a[4*q], a[4*q+1], a[4*q+2], a[4*q+3]);
    }
}

// A22 -= L21 * L21^T, 64x64 tile per CTA (lower-triangle tiles only),
// 64 threads, 8x8 microtile, transposed smem panels (pad 65 = conflict-free)
__global__ void syrk_kernel(int k0)
{
    __shared__ float Pi[NB][NB+1];
    __shared__ float Pj[NB][NB+1];
    const int b = blockIdx.y;
    int idx = blockIdx.x;
    int ti = 0;
    while ((ti+1)*(ti+2)/2 <= idx) ti++;
    int tj = idx - ti*(ti+1)/2;

    float* Mb = g_M + (size_t)b*NN*NN;
    const int gi = k0 + NB + ti*NB;
    const int gj = k0 + NB + tj*NB;
    const int tid = threadIdx.x;  // 64

    // Pi[k][i] = Mb[gi+i][k0+k]; coalesced global reads, conflict-free smem writes
    for (int r = 0; r < NB; r++) {
        Pi[tid][r] = Mb[(size_t)(gi + r)*NN + k0 + tid];
        Pj[tid][r] = Mb[(size_t)(gj + r)*NN + k0 + tid];
    }
    __syncthreads();

    const int tx = tid & 7, ty = tid >> 3;
    float acc[8][8];
    #pragma unroll
    for (int u = 0; u < 8; u++)
        #pragma unroll
        for (int v = 0; v < 8; v++) acc[u][v] = 0.0f;

    for (int kk = 0; kk < NB; kk++) {
        float av[8], bv[8];
        #pragma unroll
        for (int u = 0; u < 8; u++) av[u] = Pi[kk][ty*8 + u];
        #pragma unroll
        for (int v = 0; v < 8; v++) bv[v] = Pj[kk][tx*8 + v];
        #pragma unroll
        for (int u = 0; u < 8; u++)
            #pragma unroll
            for (int v = 0; v < 8; v++)
                acc[u][v] += av[u] * bv[v];
    }

    #pragma unroll
    for (int u = 0; u < 8; u++) {
        float* crow = Mb + (size_t)(gi + ty*8 + u)*NN + gj + tx*8;
        float4 c0 = *(float4*)(crow);
        float4 c1 = *(float4*)(crow + 4);
        c0.x -= acc[u][0]; c0.y -= acc[u][1]; c0.z -= acc[u][2]; c0.w -= acc[u][3];
        c1.x -= acc[u][4]; c1.y -= acc[u][5]; c1.z -= acc[u][6]; c1.w -= acc[u][7];
        *(float4*)(crow)     = c0;
        *(float4*)(crow + 4) = c1;
    }
}

// ---------------------------------------------------------------------------
// Triangular solves (2 RHS) + Schur combine for the bordered system
// ---------------------------------------------------------------------------
__global__ void solve_kernel(const float* __restrict__ tq, float* __restrict__ outC)
{
    __shared__ float y1[NN], y2[NN], red[NN];
    const int b = blockIdx.x, tid = threadIdx.x;  // 512 threads
    const float* Lb = g_M + (size_t)b*NN*NN;

    y1[tid] = -g_chi[b*NN + tid];
    y2[tid] = 1.0f;
    __syncthreads();

    // forward: L y = rhs
    for (int k = 0; k < NN; k++) {
        if (tid == k) {
            float inv = 1.0f / Lb[(size_t)k*NN + k];
            y1[k] *= inv; y2[k] *= inv;
        }
        __syncthreads();
        if (tid > k) {
            float l = Lb[(size_t)tid*NN + k];
            y1[tid] -= l * y1[k];
            y2[tid] -= l * y2[k];
        }
        __syncthreads();
    }
    // backward: L^T x = y  (reads row k of L -> coalesced)
    for (int k = NN-1; k >= 0; k--) {
        if (tid == k) {
            float inv = 1.0f / Lb[(size_t)k*NN + k];
            y1[k] *= inv; y2[k] *= inv;
        }
        __syncthreads();
        if (tid < k) {
            float l = Lb[(size_t)k*NN + tid];
            y1[tid] -= l * y1[k];
            y2[tid] -= l * y2[k];
        }
        __syncthreads();
    }

    // s1 = sum(x1), s2 = sum(x2)
    red[tid] = y1[tid]; __syncthreads();
    for (int s = 256; s > 0; s >>= 1) { if (tid < s) red[tid] += red[tid+s]; __syncthreads(); }
    float s1 = red[0];
    __syncthreads();
    red[tid] = y2[tid]; __syncthreads();
    for (int s = 256; s > 0; s >>= 1) { if (tid < s) red[tid] += red[tid+s]; __syncthreads(); }
    float s2 = red[0];

    float mu = (s1 - tq[b]) / s2;
    outC[b*NN + tid] = y1[tid] - mu * y2[tid];
}

// ---------------------------------------------------------------------------
extern "C" void kernel_launch(void* const* d_in, const int* in_sizes, int n_in,
                              void* d_out, int out_size)
{
    const float* pos   = (const float*)d_in[0];
    const float* nf    = (const float*)d_in[1];
    const int*   ntype = (const int*)  d_in[2];
    const float* tq    = (const float*)d_in[3];
    const float* hard  = (const float*)d_in[4];
    const float* sig   = (const float*)d_in[5];
    const float* W1    = (const float*)d_in[6];
    const float* b1    = (const float*)d_in[7];
    const float* W2    = (const float*)d_in[8];
    const float* b2    = (const float*)d_in[9];
    const float* W3    = (const float*)d_in[10];
    const float* b3    = (const float*)d_in[11];

    float* outC = (float*)d_out;          // charges (B,N)
    float* outA = (float*)d_out + BB*NN;  // A (B,N,N)

    chi_kernel<<<(BB*NN)/32, 256>>>(nf, W1, b1, W2, b2, W3, b3);
    buildA_kernel<<<dim3(NN/32, NN/32, BB), 256>>>(pos, ntype, hard, sig, outA);

    for (int s = 0; s < NSTEPS; s++) {
        int k0 = s * NB;
        potrf_kernel<<<BB, 256>>>(k0);
        int M2 = NN - k0 - NB;
        if (M2 > 0) {
            trsm_kernel<<<dim3((M2 + 127)/128, BB), 128>>>(k0);
            int T = M2 / NB;
            syrk_kernel<<<dim3(T*(T+1)/2, BB), 64>>>(k0);
        }
    }
    solve_kernel<<<BB, NN>>>(tq, outC);
}

// round 5
// speedup vs baseline: 1.5631x; 1.5631x over previous
#include <cuda_runtime.h>
#include <math.h>

#define BB 64
#define NN 512
#define DD 128
#define UU 64
#define NB 64
#define NSTEPS (NN/NB)

// Scratch (allocation-free rule: __device__ globals)
__device__ float g_M[BB*NN*NN];              // Cholesky workspace (copy of A)
__device__ float g_chi[BB*NN];
__device__ float g_Linv[NSTEPS*BB*NB*NB];    // inv of each diagonal block L11

__device__ __forceinline__ float tshrink(float x) { return x - tanhf(x); }

// ---------------------------------------------------------------------------
// chi = MLP(node_feats): 32 rows per block, 256 threads
// ---------------------------------------------------------------------------
__global__ void chi_kernel(const float* __restrict__ nf,
                           const float* __restrict__ W1, const float* __restrict__ b1,
                           const float* __restrict__ W2, const float* __restrict__ b2,
                           const float* __restrict__ W3, const float* __restrict__ b3)
{
    __shared__ float xs[32][DD];
    __shared__ float h1[32][UU];
    __shared__ float h2[32][UU];
    const int row0 = blockIdx.x * 32;
    const int tid  = threadIdx.x;

    for (int idx = tid; idx < 32*DD; idx += 256)
        xs[idx/DD][idx%DD] = nf[(size_t)row0*DD + idx];
    __syncthreads();

    for (int o = tid; o < 32*UU; o += 256) {
        int r = o / UU, u = o % UU;
        float acc = b1[u];
        #pragma unroll 8
        for (int d = 0; d < DD; d++) acc += xs[r][d] * W1[d*UU + u];
        h1[r][u] = tshrink(acc);
    }
    __syncthreads();

    for (int o = tid; o < 32*UU; o += 256) {
        int r = o / UU, u = o % UU;
        float acc = b2[u];
        #pragma unroll 8
        for (int d = 0; d < UU; d++) acc += h1[r][d] * W2[d*UU + u];
        h2[r][u] = tshrink(acc);
    }
    __syncthreads();

    if (tid < 32) {
        float acc = b3[0];
        #pragma unroll 8
        for (int d = 0; d < UU; d++) acc += h2[tid][d] * W3[d];
        g_chi[row0 + tid] = tshrink(acc);
    }
}

// ---------------------------------------------------------------------------
// Build A (B,N,N): 32x32 tile per block, write to output AND scratch
// ---------------------------------------------------------------------------
__global__ void buildA_kernel(const float* __restrict__ pos,
                              const int*   __restrict__ ntype,
                              const float* __restrict__ hardness,
                              const float* __restrict__ sigma,
                              float* __restrict__ outA)
{
    __shared__ float pix[32], piy[32], piz[32];
    __shared__ float pjx[32], pjy[32], pjz[32];
    __shared__ float si[32], sj[32], hi[32];

    const int b  = blockIdx.z;
    const int it = blockIdx.y, jt = blockIdx.x;
    const int tid = threadIdx.x;
    const float kC = 14.399645351950548f;

    if (tid < 32) {
        int gi = it*32 + tid;
        const float* p = pos + ((size_t)b*NN + gi)*3;
        pix[tid]=p[0]; piy[tid]=p[1]; piz[tid]=p[2];
        int t = ntype[b*NN + gi];
        si[tid] = sigma[t]; hi[tid] = hardness[t];
    } else if (tid < 64) {
        int l = tid - 32;
        int gj = jt*32 + l;
        const float* p = pos + ((size_t)b*NN + gj)*3;
        pjx[l]=p[0]; pjy[l]=p[1]; pjz[l]=p[2];
        sj[l] = sigma[ntype[b*NN + gj]];
    }
    __syncthreads();

    float* Ab = outA + (size_t)b*NN*NN;
    float* Mb = g_M  + (size_t)b*NN*NN;

    for (int e = tid; e < 32*32; e += 256) {
        int li = e >> 5, lj = e & 31;
        int i = it*32 + li, j = jt*32 + lj;
        float dx = pix[li]-pjx[lj], dy = piy[li]-pjy[lj], dz = piz[li]-pjz[lj];
        float dist = sqrtf(dx*dx + dy*dy + dz*dz) + 1e-8f;
        float g2 = si[li]*si[li] + sj[lj]*sj[lj];
        float arg = dist * rsqrtf(2.0f * g2);
        float a = kC * erff(arg) / dist;
        if (i == j) {
            a += hi[li] + kC / (1.7724538509055159f * 1.4142135623730951f * si[li]);
        }
        size_t off = (size_t)i*NN + j;
        Ab[off] = a;
        Mb[off] = a;
    }
}

// ---------------------------------------------------------------------------
// potrf: factor 64x64 diagonal block in smem, ALSO compute inv(L11) and
// store it to g_Linv (used by trsm-as-GEMM and the blocked solve).
// ---------------------------------------------------------------------------
__global__ void potrf_kernel(int k0, int step)
{
    __shared__ float S[NB][NB+1];
    __shared__ float X[NB][NB+1];
    __shared__ float dinv[NB];
    const int b = blockIdx.x;
    float* Mb = g_M + (size_t)b*NN*NN;
    const int tid = threadIdx.x;  // 256

    for (int idx = tid; idx < NB*NB; idx += 256)
        S[idx>>6][idx&63] = Mb[(size_t)(k0 + (idx>>6))*NN + k0 + (idx&63)];
    __syncthreads();

    for (int j = 0; j < NB; j++) {
        float invd = rsqrtf(S[j][j]);   // stable since last sync
        __syncthreads();
        if (tid >= j && tid < NB) S[tid][j] *= invd;
        __syncthreads();
        for (int idx = tid; idx < NB*NB; idx += 256) {
            int i = idx >> 6, c = idx & 63;
            if (c > j && i >= c) S[i][c] -= S[i][j] * S[c][j];
        }
        __syncthreads();
    }

    for (int idx = tid; idx < NB*NB; idx += 256)
        Mb[(size_t)(k0 + (idx>>6))*NN + k0 + (idx&63)] = S[idx>>6][idx&63];

    if (tid < NB) dinv[tid] = 1.0f / S[tid][tid];
    __syncthreads();

    // invert L11: thread j owns column j (fully private, branch-free:
    // X[p][j]=0 for p<j makes the extra terms no-ops)
    if (tid < NB) {
        const int j = tid;
        for (int i = 0; i < NB; i++) {
            float acc = (i == j) ? 1.0f : 0.0f;
            for (int p = j; p < i; p++) acc -= S[i][p] * X[p][j];
            X[i][j] = acc * dinv[i];
        }
    }
    __syncthreads();

    float* Xb = g_Linv + ((size_t)step*BB + b)*NB*NB;
    for (int idx = tid; idx < NB*NB; idx += 256)
        Xb[idx] = X[idx>>6][idx&63];
}

// ---------------------------------------------------------------------------
// trsm as GEMM: L21(tile) = A21(tile) * invL11^T.
// 64x64 tile per CTA, 256 threads, 4x4 microtile.
// ---------------------------------------------------------------------------
__global__ void trsm_kernel(int k0, int step)
{
    __shared__ float As[NB][NB+4];  // As[k][i] = A[i][k]
    __shared__ float Xs[NB][NB+4];  // Xs[k][j] = invL[j][k]
    const int b = blockIdx.y;
    float* Mb = g_M + (size_t)b*NN*NN;
    const float* Xb = g_Linv + ((size_t)step*BB + b)*NB*NB;
    const int gi = k0 + NB + blockIdx.x*NB;
    const int tid = threadIdx.x;  // 256

    for (int idx = tid; idx < NB*NB; idx += 256) {
        int i = idx >> 6, k = idx & 63;
        As[k][i] = Mb[(size_t)(gi + i)*NN + k0 + k];
        Xs[k][i] = Xb[i*NB + k];
    }
    __syncthreads();

    const int tx = tid & 15, ty = tid >> 4;
    float acc[4][4];
    #pragma unroll
    for (int u = 0; u < 4; u++)
        #pragma unroll
        for (int v = 0; v < 4; v++) acc[u][v] = 0.0f;

    #pragma unroll 4
    for (int k = 0; k < NB; k++) {
        float a[4], xv[4];
        #pragma unroll
        for (int u = 0; u < 4; u++) a[u]  = As[k][ty*4 + u];
        #pragma unroll
        for (int v = 0; v < 4; v++) xv[v] = Xs[k][tx*4 + v];
        #pragma unroll
        for (int u = 0; u < 4; u++)
            #pragma unroll
            for (int v = 0; v < 4; v++)
                acc[u][v] += a[u] * xv[v];
    }

    #pragma unroll
    for (int u = 0; u < 4; u++) {
        float4 c = make_float4(acc[u][0], acc[u][1], acc[u][2], acc[u][3]);
        *(float4*)(Mb + (size_t)(gi + ty*4 + u)*NN + k0 + tx*4) = c;
    }
}

// ---------------------------------------------------------------------------
// A22 -= L21 * L21^T, 64x64 tile per CTA (lower-triangle tiles only)
// ---------------------------------------------------------------------------
__global__ void syrk_kernel(int k0)
{
    __shared__ float Pi[NB][NB+1];
    __shared__ float Pj[NB][NB+1];
    const int b = blockIdx.y;
    int idx = blockIdx.x;
    int ti = 0;
    while ((ti+1)*(ti+2)/2 <= idx) ti++;
    int tj = idx - ti*(ti+1)/2;

    float* Mb = g_M + (size_t)b*NN*NN;
    const int gi = k0 + NB + ti*NB;
    const int gj = k0 + NB + tj*NB;
    const int tid = threadIdx.x;  // 64

    for (int r = 0; r < NB; r++) {
        Pi[tid][r] = Mb[(size_t)(gi + r)*NN + k0 + tid];
        Pj[tid][r] = Mb[(size_t)(gj + r)*NN + k0 + tid];
    }
    __syncthreads();

    const int tx = tid & 7, ty = tid >> 3;
    float acc[8][8];
    #pragma unroll
    for (int u = 0; u < 8; u++)
        #pragma unroll
        for (int v = 0; v < 8; v++) acc[u][v] = 0.0f;

    for (int kk = 0; kk < NB; kk++) {
        float av[8], bv[8];
        #pragma unroll
        for (int u = 0; u < 8; u++) av[u] = Pi[kk][ty*8 + u];
        #pragma unroll
        for (int v = 0; v < 8; v++) bv[v] = Pj[kk][tx*8 + v];
        #pragma unroll
        for (int u = 0; u < 8; u++)
            #pragma unroll
            for (int v = 0; v < 8; v++)
                acc[u][v] += av[u] * bv[v];
    }

    #pragma unroll
    for (int u = 0; u < 8; u++) {
        float* crow = Mb + (size_t)(gi + ty*8 + u)*NN + gj + tx*8;
        float4 c0 = *(float4*)(crow);
        float4 c1 = *(float4*)(crow + 4);
        c0.x -= acc[u][0]; c0.y -= acc[u][1]; c0.z -= acc[u][2]; c0.w -= acc[u][3];
        c1.x -= acc[u][4]; c1.y -= acc[u][5]; c1.z -= acc[u][6]; c1.w -= acc[u][7];
        *(float4*)(crow)     = c0;
        *(float4*)(crow + 4) = c1;
    }
}

// ---------------------------------------------------------------------------
// Blocked triangular solves (2 RHS) + Schur combine.
// Diagonal blocks applied via precomputed inverses (matvec, no serial chains).
// 64 CTAs (one per batch), 256 threads: 4 threads per row (quad-split dots).
// ---------------------------------------------------------------------------
__global__ void solve_kernel(const float* __restrict__ tq, float* __restrict__ outC)
{
    __shared__ float y1[NN], y2[NN];
    __shared__ float Bs[NB][NB+1];
    __shared__ float u1[NB], u2[NB];
    __shared__ float r1[8], r2[8];
    const int b = blockIdx.x, tid = threadIdx.x;  // 256
    const float* Mb = g_M + (size_t)b*NN*NN;
    const int r = tid >> 2, q = tid & 3;

    for (int i = tid; i < NN; i += 256) { y1[i] = -g_chi[b*NN + i]; y2[i] = 1.0f; }
    __syncthreads();

    // ---- forward: L y = rhs
    for (int s = 0; s < NSTEPS; s++) {
        float a1 = 0.0f, a2 = 0.0f;
        for (int t = 0; t < s; t++) {
            for (int idx = tid; idx < NB*NB; idx += 256)
                Bs[idx>>6][idx&63] = Mb[(size_t)(s*NB + (idx>>6))*NN + t*NB + (idx&63)];
            __syncthreads();
            for (int k = q; k < NB; k += 4) {
                float w = Bs[r][k];
                a1 += w * y1[t*NB + k];
                a2 += w * y2[t*NB + k];
            }
            __syncthreads();
        }
        a1 += __shfl_xor_sync(0xffffffffu, a1, 1);
        a1 += __shfl_xor_sync(0xffffffffu, a1, 2);
        a2 += __shfl_xor_sync(0xffffffffu, a2, 1);
        a2 += __shfl_xor_sync(0xffffffffu, a2, 2);
        if (q == 0) { u1[r] = y1[s*NB + r] - a1; u2[r] = y2[s*NB + r] - a2; }

        const float* Xb = g_Linv + ((size_t)s*BB + b)*NB*NB;
        for (int idx = tid; idx < NB*NB; idx += 256)
            Bs[idx>>6][idx&63] = Xb[idx];
        __syncthreads();

        float z1 = 0.0f, z2 = 0.0f;
        for (int k = q; k < NB; k += 4) {
            float w = Bs[r][k];           // invL[r][k]
            z1 += w * u1[k];
            z2 += w * u2[k];
        }
        z1 += __shfl_xor_sync(0xffffffffu, z1, 1);
        z1 += __shfl_xor_sync(0xffffffffu, z1, 2);
        z2 += __shfl_xor_sync(0xffffffffu, z2, 1);
        z2 += __shfl_xor_sync(0xffffffffu, z2, 2);
        if (q == 0) { y1[s*NB + r] = z1; y2[s*NB + r] = z2; }
        __syncthreads();
    }

    // ---- backward: L^T x = y
    for (int s = NSTEPS - 1; s >= 0; s--) {
        float a1 = 0.0f, a2 = 0.0f;
        for (int t = s + 1; t < NSTEPS; t++) {
            for (int idx = tid; idx < NB*NB; idx += 256)
                Bs[idx>>6][idx&63] = Mb[(size_t)(t*NB + (idx>>6))*NN + s*NB + (idx&63)];
            __syncthreads();
            for (int k = q; k < NB; k += 4) {
                float w = Bs[k][r];       // L[t*NB+k][s*NB+r] (transposed use)
                a1 += w * y1[t*NB + k];
                a2 += w * y2[t*NB + k];
            }
            __syncthreads();
        }
        a1 += __shfl_xor_sync(0xffffffffu, a1, 1);
        a1 += __shfl_xor_sync(0xffffffffu, a1, 2);
        a2 += __shfl_xor_sync(0xffffffffu, a2, 1);
        a2 += __shfl_xor_sync(0xffffffffu, a2, 2);
        if (q == 0) { u1[r] = y1[s*NB + r] - a1; u2[r] = y2[s*NB + r] - a2; }

        const float* Xb = g_Linv + ((size_t)s*BB + b)*NB*NB;
        for (int idx = tid; idx < NB*NB; idx += 256)
            Bs[idx>>6][idx&63] = Xb[idx];
        __syncthreads();

        float z1 = 0.0f, z2 = 0.0f;
        for (int k = q; k < NB; k += 4) {
            float w = Bs[k][r];           // invL[k][r] = (invL^T)[r][k]
            z1 += w * u1[k];
            z2 += w * u2[k];
        }
        z1 += __shfl_xor_sync(0xffffffffu, z1, 1);
        z1 += __shfl_xor_sync(0xffffffffu, z1, 2);
        z2 += __shfl_xor_sync(0xffffffffu, z2, 1);
        z2 += __shfl_xor_sync(0xffffffffu, z2, 2);
        if (q == 0) { y1[s*NB + r] = z1; y2[s*NB + r] = z2; }
        __syncthreads();
    }

    // ---- Schur combine: mu = (1^T x1 - Q) / (1^T x2);  q = x1 - mu*x2
    float s1 = 0.0f, s2 = 0.0f;
    for (int i = tid; i < NN; i += 256) { s1 += y1[i]; s2 += y2[i]; }
    #pragma unroll
    for (int o = 16; o > 0; o >>= 1) {
        s1 += __shfl_xor_sync(0xffffffffu, s1, o);
        s2 += __shfl_xor_sync(0xffffffffu, s2, o);
    }
    if ((tid & 31) == 0) { r1[tid >> 5] = s1; r2[tid >> 5] = s2; }
    __syncthreads();
    if (tid == 0) {
        float S1 = 0.0f, S2 = 0.0f;
        for (int w = 0; w < 8; w++) { S1 += r1[w]; S2 += r2[w]; }
        r1[0] = (S1 - tq[b]) / S2;
    }
    __syncthreads();
    float mu = r1[0];
    for (int i = tid; i < NN; i += 256)
        outC[b*NN + i] = y1[i] - mu * y2[i];
}

// ---------------------------------------------------------------------------
extern "C" void kernel_launch(void* const* d_in, const int* in_sizes, int n_in,
                              void* d_out, int out_size)
{
    const float* pos   = (const float*)d_in[0];
    const float* nf    = (const float*)d_in[1];
    const int*   ntype = (const int*)  d_in[2];
    const float* tq    = (const float*)d_in[3];
    const float* hard  = (const float*)d_in[4];
    const float* sig   = (const float*)d_in[5];
    const float* W1    = (const float*)d_in[6];
    const float* b1    = (const float*)d_in[7];
    const float* W2    = (const float*)d_in[8];
    const float* b2    = (const float*)d_in[9];
    const float* W3    = (const float*)d_in[10];
    const float* b3    = (const float*)d_in[11];

    float* outC = (float*)d_out;          // charges (B,N)
    float* outA = (float*)d_out + BB*NN;  // A (B,N,N)

    chi_kernel<<<(BB*NN)/32, 256>>>(nf, W1, b1, W2, b2, W3, b3);
    buildA_kernel<<<dim3(NN/32, NN/32, BB), 256>>>(pos, ntype, hard, sig, outA);

    for (int s = 0; s < NSTEPS; s++) {
        int k0 = s * NB;
        potrf_kernel<<<BB, 256>>>(k0, s);
        int M2 = NN - k0 - NB;
        if (M2 > 0) {
            int R = M2 / NB;
            trsm_kernel<<<dim3(R, BB), 256>>>(k0, s);
            syrk_kernel<<<dim3(R*(R+1)/2, BB), 64>>>(k0);
        }
    }
    solve_kernel<<<BB, 256>>>(tq, outC);
}

// round 6
// speedup vs baseline: 1.9530x; 1.2495x over previous
#include <cuda_runtime.h>
#include <math.h>

#define BB 64
#define NN 512
#define DD 128
#define UU 64
#define NB 64
#define NSTEPS (NN/NB)

// Scratch (allocation-free rule: __device__ globals)
__device__ float g_M[BB*NN*NN];              // Cholesky workspace (copy of A)
__device__ float g_chi[BB*NN];
__device__ float g_Linv[NSTEPS*BB*NB*NB];    // inv of each diagonal block L11

__device__ __forceinline__ float tshrink(float x) { return x - tanhf(x); }

// ---------------------------------------------------------------------------
// chi = MLP(node_feats): 32 rows per block, 256 threads.
// Register-tiled: thread = (u, row-group of 8); transposed activations in smem
// so each d-iter is 1 coalesced W load + 2 LDS.128 for 8 FFMA.
// ---------------------------------------------------------------------------
__global__ __launch_bounds__(256) void chi_kernel(
    const float* __restrict__ nf,
    const float* __restrict__ W1, const float* __restrict__ b1,
    const float* __restrict__ W2, const float* __restrict__ b2,
    const float* __restrict__ W3, const float* __restrict__ b3)
{
    __shared__ float xs_t[DD][36];   // [d][r], 32 rows padded to 36
    __shared__ float h1_t[UU][36];
    __shared__ float h2_t[UU][36];
    const int row0 = blockIdx.x * 32;
    const int tid  = threadIdx.x;
    const int u  = tid & 63;
    const int r0 = (tid >> 6) * 8;

    // load 32 rows x 128 cols transposed (float4 global loads)
    #pragma unroll
    for (int t = 0; t < 4; t++) {
        int f = tid + 256*t;          // f < 1024
        int r = f >> 5, c4 = f & 31;
        float4 v = *(const float4*)(nf + (size_t)(row0 + r)*DD + c4*4);
        xs_t[c4*4+0][r] = v.x;
        xs_t[c4*4+1][r] = v.y;
        xs_t[c4*4+2][r] = v.z;
        xs_t[c4*4+3][r] = v.w;
    }
    __syncthreads();

    // layer 1: h1 = tshrink(x @ W1 + b1)
    {
        float acc[8];
        float bias = b1[u];
        #pragma unroll
        for (int m = 0; m < 8; m++) acc[m] = bias;
        #pragma unroll 4
        for (int d = 0; d < DD; d++) {
            float w = W1[d*UU + u];
            float4 xa = *(const float4*)&xs_t[d][r0];
            float4 xb = *(const float4*)&xs_t[d][r0+4];
            acc[0] += xa.x*w; acc[1] += xa.y*w; acc[2] += xa.z*w; acc[3] += xa.w*w;
            acc[4] += xb.x*w; acc[5] += xb.y*w; acc[6] += xb.z*w; acc[7] += xb.w*w;
        }
        float4 o0 = make_float4(tshrink(acc[0]), tshrink(acc[1]), tshrink(acc[2]), tshrink(acc[3]));
        float4 o1 = make_float4(tshrink(acc[4]), tshrink(acc[5]), tshrink(acc[6]), tshrink(acc[7]));
        *(float4*)&h1_t[u][r0]   = o0;
        *(float4*)&h1_t[u][r0+4] = o1;
    }
    __syncthreads();

    // layer 2
    {
        float acc[8];
        float bias = b2[u];
        #pragma unroll
        for (int m = 0; m < 8; m++) acc[m] = bias;
        #pragma unroll 4
        for (int d = 0; d < UU; d++) {
            float w = W2[d*UU + u];
            float4 xa = *(const float4*)&h1_t[d][r0];
            float4 xb = *(const float4*)&h1_t[d][r0+4];
            acc[0] += xa.x*w; acc[1] += xa.y*w; acc[2] += xa.z*w; acc[3] += xa.w*w;
            acc[4] += xb.x*w; acc[5] += xb.y*w; acc[6] += xb.z*w; acc[7] += xb.w*w;
        }
        float4 o0 = make_float4(tshrink(acc[0]), tshrink(acc[1]), tshrink(acc[2]), tshrink(acc[3]));
        float4 o1 = make_float4(tshrink(acc[4]), tshrink(acc[5]), tshrink(acc[6]), tshrink(acc[7]));
        *(float4*)&h2_t[u][r0]   = o0;
        *(float4*)&h2_t[u][r0+4] = o1;
    }
    __syncthreads();

    // layer 3: chi[r] = tshrink(h2[r] . W3 + b3); 8 threads per row
    {
        int r = tid >> 3, s = tid & 7;   // r in 0..31
        float acc = 0.0f;
        #pragma unroll
        for (int k = 0; k < 8; k++) {
            int uu = s + 8*k;
            acc += h2_t[uu][r] * W3[uu];
        }
        acc += __shfl_xor_sync(0xffffffffu, acc, 1);
        acc += __shfl_xor_sync(0xffffffffu, acc, 2);
        acc += __shfl_xor_sync(0xffffffffu, acc, 4);
        if (s == 0) g_chi[row0 + r] = tshrink(acc + b3[0]);
    }
}

// ---------------------------------------------------------------------------
// Build A (B,N,N): 32x32 tile per block, write to output AND scratch
// ---------------------------------------------------------------------------
__global__ __launch_bounds__(256) void buildA_kernel(
    const float* __restrict__ pos,
    const int*   __restrict__ ntype,
    const float* __restrict__ hardness,
    const float* __restrict__ sigma,
    float* __restrict__ outA)
{
    __shared__ float pix[32], piy[32], piz[32];
    __shared__ float pjx[32], pjy[32], pjz[32];
    __shared__ float si[32], sj[32], hi[32];

    const int b  = blockIdx.z;
    const int it = blockIdx.y, jt = blockIdx.x;
    const int tid = threadIdx.x;
    const float kC = 14.399645351950548f;

    if (tid < 32) {
        int gi = it*32 + tid;
        const float* p = pos + ((size_t)b*NN + gi)*3;
        pix[tid]=p[0]; piy[tid]=p[1]; piz[tid]=p[2];
        int t = ntype[b*NN + gi];
        si[tid] = sigma[t]; hi[tid] = hardness[t];
    } else if (tid < 64) {
        int l = tid - 32;
        int gj = jt*32 + l;
        const float* p = pos + ((size_t)b*NN + gj)*3;
        pjx[l]=p[0]; pjy[l]=p[1]; pjz[l]=p[2];
        sj[l] = sigma[ntype[b*NN + gj]];
    }
    __syncthreads();

    float* Ab = outA + (size_t)b*NN*NN;
    float* Mb = g_M  + (size_t)b*NN*NN;

    for (int e = tid; e < 32*32; e += 256) {
        int li = e >> 5, lj = e & 31;
        int i = it*32 + li, j = jt*32 + lj;
        float dx = pix[li]-pjx[lj], dy = piy[li]-pjy[lj], dz = piz[li]-pjz[lj];
        float dist = sqrtf(dx*dx + dy*dy + dz*dz) + 1e-8f;
        float g2 = si[li]*si[li] + sj[lj]*sj[lj];
        float arg = dist * rsqrtf(2.0f * g2);
        float a = kC * erff(arg) / dist;
        if (i == j) {
            a += hi[li] + kC / (1.7724538509055159f * 1.4142135623730951f * si[li]);
        }
        size_t off = (size_t)i*NN + j;
        Ab[off] = a;
        Mb[off] = a;
    }
}

// ---------------------------------------------------------------------------
// potrf: LDL-style elimination (1 barrier/iter) + deferred scaling, then
// block 2x2 inversion of L11 (two warp-local 32x32 inversions + 2 small GEMMs).
// ---------------------------------------------------------------------------
__global__ __launch_bounds__(256) void potrf_kernel(int k0, int step)
{
    __shared__ float S[NB][NB+4];
    __shared__ float X[NB][NB+4];
    __shared__ float Tt[32][33];
    __shared__ float dinv[NB];
    const int b = blockIdx.x;
    float* Mb = g_M + (size_t)b*NN*NN;
    const int tid = threadIdx.x;  // 256

    for (int idx = tid; idx < NB*NB; idx += 256)
        S[idx>>6][idx&63] = Mb[(size_t)(k0 + (idx>>6))*NN + k0 + (idx&63)];
    __syncthreads();

    // elimination: writes only to columns c>j; reads only column j (frozen)
    for (int j = 0; j < NB; j++) {
        float invd = 1.0f / S[j][j];
        for (int idx = tid; idx < NB*NB; idx += 256) {
            int i = idx >> 6, c = idx & 63;
            if (c > j && i >= c) S[i][c] -= S[i][j] * (S[c][j] * invd);
        }
        __syncthreads();
    }

    // deferred scaling: L[i][j] = S[i][j] * rsqrt(D[j]); dinv[j] = 1/L[j][j]
    if (tid < NB) dinv[tid] = rsqrtf(S[tid][tid]);
    __syncthreads();
    for (int idx = tid; idx < NB*NB; idx += 256) {
        int i = idx >> 6, c = idx & 63;
        if (i >= c) S[i][c] *= dinv[c];
    }
    __syncthreads();

    for (int idx = tid; idx < NB*NB; idx += 256)
        Mb[(size_t)(k0 + (idx>>6))*NN + k0 + (idx&63)] = S[idx>>6][idx&63];

    // ---- invert L (lower-tri, now in S): block 2x2 formula.
    // Phase A: invert the two 32x32 diagonal blocks, one warp each.
    // (column j computed top-down; rows i<j come out exactly 0)
    if (tid < 64) {
        int h = tid >> 5, j = tid & 31, base = h * 32;
        for (int i = 0; i < 32; i++) {
            float acc = (i == j) ? 1.0f : 0.0f;
            for (int p = 0; p < i; p++)
                acc -= S[base+i][base+p] * X[base+p][base+j];
            X[base+i][base+j] = acc * dinv[base+i];
            __syncwarp();
        }
    }
    __syncthreads();
    // Phase B: Tt = L21 * X1 ; also zero upper-right block of X
    for (int idx = tid; idx < 32*32; idx += 256) {
        int i = idx >> 5, j = idx & 31;
        float acc = 0.0f;
        #pragma unroll 8
        for (int p = 0; p < 32; p++) acc += S[32+i][p] * X[p][j];
        Tt[i][j] = acc;
        X[i][32+j] = 0.0f;
    }
    __syncthreads();
    // Phase C: X21 = -X2 * Tt
    for (int idx = tid; idx < 32*32; idx += 256) {
        int i = idx >> 5, j = idx & 31;
        float acc = 0.0f;
        #pragma unroll 8
        for (int p = 0; p < 32; p++) acc += X[32+i][32+p] * Tt[p][j];
        X[32+i][j] = -acc;
    }
    __syncthreads();

    float* Xb = g_Linv + ((size_t)step*BB + b)*NB*NB;
    for (int idx = tid; idx < NB*NB; idx += 256)
        Xb[idx] = X[idx>>6][idx&63];
}

// ---------------------------------------------------------------------------
// trsm as GEMM: L21(tile) = A21(tile) * invL11^T.
// 64x64 tile per CTA, 256 threads, 4x4 microtile, LDS.128 operands.
// ---------------------------------------------------------------------------
__global__ __launch_bounds__(256) void trsm_kernel(int k0, int step)
{
    __shared__ float As[NB][NB+4];  // As[k][i] = A[i][k]
    __shared__ float Xs[NB][NB+4];  // Xs[k][j] = invL[j][k]
    const int b = blockIdx.y;
    float* Mb = g_M + (size_t)b*NN*NN;
    const float* Xb = g_Linv + ((size_t)step*BB + b)*NB*NB;
    const int gi = k0 + NB + blockIdx.x*NB;
    const int tid = threadIdx.x;  // 256

    for (int idx = tid; idx < NB*NB; idx += 256) {
        int i = idx >> 6, k = idx & 63;
        As[k][i] = Mb[(size_t)(gi + i)*NN + k0 + k];
        Xs[k][i] = Xb[i*NB + k];
    }
    __syncthreads();

    const int tx = tid & 15, ty = tid >> 4;
    float acc[4][4];
    #pragma unroll
    for (int u = 0; u < 4; u++)
        #pragma unroll
        for (int v = 0; v < 4; v++) acc[u][v] = 0.0f;

    #pragma unroll 4
    for (int k = 0; k < NB; k++) {
        float4 a = *(const float4*)&As[k][ty*4];
        float4 x = *(const float4*)&Xs[k][tx*4];
        float av[4] = {a.x, a.y, a.z, a.w};
        float xv[4] = {x.x, x.y, x.z, x.w};
        #pragma unroll
        for (int u = 0; u < 4; u++)
            #pragma unroll
            for (int v = 0; v < 4; v++)
                acc[u][v] += av[u] * xv[v];
    }

    #pragma unroll
    for (int u = 0; u < 4; u++) {
        float4 c = make_float4(acc[u][0], acc[u][1], acc[u][2], acc[u][3]);
        *(float4*)(Mb + (size_t)(gi + ty*4 + u)*NN + k0 + tx*4) = c;
    }
}

// ---------------------------------------------------------------------------
// A22 -= L21 * L21^T, 64x64 tile per CTA (lower-triangle tiles only),
// 64 threads, 8x8 microtile, LDS.128 operands.
// ---------------------------------------------------------------------------
__global__ __launch_bounds__(64) void syrk_kernel(int k0)
{
    __shared__ float Pi[NB][NB+4];
    __shared__ float Pj[NB][NB+4];
    const int b = blockIdx.y;
    int idx = blockIdx.x;
    int ti = 0;
    while ((ti+1)*(ti+2)/2 <= idx) ti++;
    int tj = idx - ti*(ti+1)/2;

    float* Mb = g_M + (size_t)b*NN*NN;
    const int gi = k0 + NB + ti*NB;
    const int gj = k0 + NB + tj*NB;
    const int tid = threadIdx.x;  // 64

    for (int r = 0; r < NB; r++) {
        Pi[tid][r] = Mb[(size_t)(gi + r)*NN + k0 + tid];
        Pj[tid][r] = Mb[(size_t)(gj + r)*NN + k0 + tid];
    }
    __syncthreads();

    const int tx = tid & 7, ty = tid >> 3;
    float acc[8][8];
    #pragma unroll
    for (int u = 0; u < 8; u++)
        #pragma unroll
        for (int v = 0; v < 8; v++) acc[u][v] = 0.0f;

    #pragma unroll 2
    for (int kk = 0; kk < NB; kk++) {
        float4 a0 = *(const float4*)&Pi[kk][ty*8];
        float4 a1 = *(const float4*)&Pi[kk][ty*8+4];
        float4 b0 = *(const float4*)&Pj[kk][tx*8];
        float4 b1 = *(const float4*)&Pj[kk][tx*8+4];
        float av[8] = {a0.x,a0.y,a0.z,a0.w, a1.x,a1.y,a1.z,a1.w};
        float bv[8] = {b0.x,b0.y,b0.z,b0.w, b1.x,b1.y,b1.z,b1.w};
        #pragma unroll
        for (int u = 0; u < 8; u++)
            #pragma unroll
            for (int v = 0; v < 8; v++)
                acc[u][v] += av[u] * bv[v];
    }

    #pragma unroll
    for (int u = 0; u < 8; u++) {
        float* crow = Mb + (size_t)(gi + ty*8 + u)*NN + gj + tx*8;
        float4 c0 = *(float4*)(crow);
        float4 c1 = *(float4*)(crow + 4);
        c0.x -= acc[u][0]; c0.y -= acc[u][1]; c0.z -= acc[u][2]; c0.w -= acc[u][3];
        c1.x -= acc[u][4]; c1.y -= acc[u][5]; c1.z -= acc[u][6]; c1.w -= acc[u][7];
        *(float4*)(crow)     = c0;
        *(float4*)(crow + 4) = c1;
    }
}

// ---------------------------------------------------------------------------
// Blocked triangular solves (2 RHS) + Schur combine.
// ---------------------------------------------------------------------------
__global__ __launch_bounds__(256) void solve_kernel(const float* __restrict__ tq,
                                                    float* __restrict__ outC)
{
    __shared__ float y1[NN], y2[NN];
    __shared__ float Bs[NB][NB+1];
    __shared__ float u1[NB], u2[NB];
    __shared__ float r1[8], r2[8];
    const int b = blockIdx.x, tid = threadIdx.x;  // 256
    const float* Mb = g_M + (size_t)b*NN*NN;
    const int r = tid >> 2, q = tid & 3;

    for (int i = tid; i < NN; i += 256) { y1[i] = -g_chi[b*NN + i]; y2[i] = 1.0f; }
    __syncthreads();

    // ---- forward: L y = rhs
    for (int s = 0; s < NSTEPS; s++) {
        float a1 = 0.0f, a2 = 0.0f;
        for (int t = 0; t < s; t++) {
            for (int idx = tid; idx < NB*NB; idx += 256)
                Bs[idx>>6][idx&63] = Mb[(size_t)(s*NB + (idx>>6))*NN + t*NB + (idx&63)];
            __syncthreads();
            for (int k = q; k < NB; k += 4) {
                float w = Bs[r][k];
                a1 += w * y1[t*NB + k];
                a2 += w * y2[t*NB + k];
            }
            __syncthreads();
        }
        a1 += __shfl_xor_sync(0xffffffffu, a1, 1);
        a1 += __shfl_xor_sync(0xffffffffu, a1, 2);
        a2 += __shfl_xor_sync(0xffffffffu, a2, 1);
        a2 += __shfl_xor_sync(0xffffffffu, a2, 2);
        if (q == 0) { u1[r] = y1[s*NB + r] - a1; u2[r] = y2[s*NB + r] - a2; }

        const float* Xb = g_Linv + ((size_t)s*BB + b)*NB*NB;
        for (int idx = tid; idx < NB*NB; idx += 256)
            Bs[idx>>6][idx&63] = Xb[idx];
        __syncthreads();

        float z1 = 0.0f, z2 = 0.0f;
        for (int k = q; k < NB; k += 4) {
            float w = Bs[r][k];           // invL[r][k]
            z1 += w * u1[k];
            z2 += w * u2[k];
        }
        z1 += __shfl_xor_sync(0xffffffffu, z1, 1);
        z1 += __shfl_xor_sync(0xffffffffu, z1, 2);
        z2 += __shfl_xor_sync(0xffffffffu, z2, 1);
        z2 += __shfl_xor_sync(0xffffffffu, z2, 2);
        if (q == 0) { y1[s*NB + r] = z1; y2[s*NB + r] = z2; }
        __syncthreads();
    }

    // ---- backward: L^T x = y
    for (int s = NSTEPS - 1; s >= 0; s--) {
        float a1 = 0.0f, a2 = 0.0f;
        for (int t = s + 1; t < NSTEPS; t++) {
            for (int idx = tid; idx < NB*NB; idx += 256)
                Bs[idx>>6][idx&63] = Mb[(size_t)(t*NB + (idx>>6))*NN + s*NB + (idx&63)];
            __syncthreads();
            for (int k = q; k < NB; k += 4) {
                float w = Bs[k][r];       // transposed use
                a1 += w * y1[t*NB + k];
                a2 += w * y2[t*NB + k];
            }
            __syncthreads();
        }
        a1 += __shfl_xor_sync(0xffffffffu, a1, 1);
        a1 += __shfl_xor_sync(0xffffffffu, a1, 2);
        a2 += __shfl_xor_sync(0xffffffffu, a2, 1);
        a2 += __shfl_xor_sync(0xffffffffu, a2, 2);
        if (q == 0) { u1[r] = y1[s*NB + r] - a1; u2[r] = y2[s*NB + r] - a2; }

        const float* Xb = g_Linv + ((size_t)s*BB + b)*NB*NB;
        for (int idx = tid; idx < NB*NB; idx += 256)
            Bs[idx>>6][idx&63] = Xb[idx];
        __syncthreads();

        float z1 = 0.0f, z2 = 0.0f;
        for (int k = q; k < NB; k += 4) {
            float w = Bs[k][r];           // invL^T
            z1 += w * u1[k];
            z2 += w * u2[k];
        }
        z1 += __shfl_xor_sync(0xffffffffu, z1, 1);
        z1 += __shfl_xor_sync(0xffffffffu, z1, 2);
        z2 += __shfl_xor_sync(0xffffffffu, z2, 1);
        z2 += __shfl_xor_sync(0xffffffffu, z2, 2);
        if (q == 0) { y1[s*NB + r] = z1; y2[s*NB + r] = z2; }
        __syncthreads();
    }

    // ---- Schur combine
    float s1 = 0.0f, s2 = 0.0f;
    for (int i = tid; i < NN; i += 256) { s1 += y1[i]; s2 += y2[i]; }
    #pragma unroll
    for (int o = 16; o > 0; o >>= 1) {
        s1 += __shfl_xor_sync(0xffffffffu, s1, o);
        s2 += __shfl_xor_sync(0xffffffffu, s2, o);
    }
    if ((tid & 31) == 0) { r1[tid >> 5] = s1; r2[tid >> 5] = s2; }
    __syncthreads();
    if (tid == 0) {
        float S1 = 0.0f, S2 = 0.0f;
        for (int w = 0; w < 8; w++) { S1 += r1[w]; S2 += r2[w]; }
        r1[0] = (S1 - tq[b]) / S2;
    }
    __syncthreads();
    float mu = r1[0];
    for (int i = tid; i < NN; i += 256)
        outC[b*NN + i] = y1[i] - mu * y2[i];
}

// ---------------------------------------------------------------------------
extern "C" void kernel_launch(void* const* d_in, const int* in_sizes, int n_in,
                              void* d_out, int out_size)
{
    const float* pos   = (const float*)d_in[0];
    const float* nf    = (const float*)d_in[1];
    const int*   ntype = (const int*)  d_in[2];
    const float* tq    = (const float*)d_in[3];
    const float* hard  = (const float*)d_in[4];
    const float* sig   = (const float*)d_in[5];
    const float* W1    = (const float*)d_in[6];
    const float* b1    = (const float*)d_in[7];
    const float* W2    = (const float*)d_in[8];
    const float* b2    = (const float*)d_in[9];
    const float* W3    = (const float*)d_in[10];
    const float* b3    = (const float*)d_in[11];

    float* outC = (float*)d_out;          // charges (B,N)
    float* outA = (float*)d_out + BB*NN;  // A (B,N,N)

    chi_kernel<<<(BB*NN)/32, 256>>>(nf, W1, b1, W2, b2, W3, b3);
    buildA_kernel<<<dim3(NN/32, NN/32, BB), 256>>>(pos, ntype, hard, sig, outA);

    for (int s = 0; s < NSTEPS; s++) {
        int k0 = s * NB;
        potrf_kernel<<<BB, 256>>>(k0, s);
        int M2 = NN - k0 - NB;
        if (M2 > 0) {
            int R = M2 / NB;
            trsm_kernel<<<dim3(R, BB), 256>>>(k0, s);
            syrk_kernel<<<dim3(R*(R+1)/2, BB), 64>>>(k0);
        }
    }
    solve_kernel<<<BB, 256>>>(tq, outC);
}

// round 7
// speedup vs baseline: 2.3374x; 1.1968x over previous
#include <cuda_runtime.h>
#include <math.h>

#define BB 64
#define NN 512
#define DD 128
#define UU 64
#define NB 64
#define NSTEPS (NN/NB)

#define PSTRIDE 449              // odd -> conflict-free transposed panel stores
#define OFF_S   28736            // 64*449
#define OFF_X   (OFF_S + 64*65)
#define OFF_XT  (OFF_X + 64*65)
#define OFF_TT  (OFF_XT + 64*65)
#define OFF_DI  (OFF_TT + 32*33)
#define SMEM_FLOATS (OFF_DI + 64)
#define SMEM_BYTES (SMEM_FLOATS*4)   // 169,344 B

// Scratch (allocation-free rule: __device__ globals)
__device__ float g_M[BB*NN*NN];              // Cholesky workspace (copy of A)
__device__ float g_chi[BB*NN];
__device__ float g_Linv[NSTEPS*BB*NB*NB];    // inv of each diagonal block L11

__device__ __forceinline__ float tshrink(float x) { return x - tanhf(x); }

// ---------------------------------------------------------------------------
// chi = MLP(node_feats): 32 rows per block, 256 threads (register-tiled)
// ---------------------------------------------------------------------------
__global__ __launch_bounds__(256) void chi_kernel(
    const float* __restrict__ nf,
    const float* __restrict__ W1, const float* __restrict__ b1,
    const float* __restrict__ W2, const float* __restrict__ b2,
    const float* __restrict__ W3, const float* __restrict__ b3)
{
    __shared__ float xs_t[DD][36];
    __shared__ float h1_t[UU][36];
    __shared__ float h2_t[UU][36];
    const int row0 = blockIdx.x * 32;
    const int tid  = threadIdx.x;
    const int u  = tid & 63;
    const int r0 = (tid >> 6) * 8;

    #pragma unroll
    for (int t = 0; t < 4; t++) {
        int f = tid + 256*t;
        int r = f >> 5, c4 = f & 31;
        float4 v = *(const float4*)(nf + (size_t)(row0 + r)*DD + c4*4);
        xs_t[c4*4+0][r] = v.x;
        xs_t[c4*4+1][r] = v.y;
        xs_t[c4*4+2][r] = v.z;
        xs_t[c4*4+3][r] = v.w;
    }
    __syncthreads();

    {
        float acc[8];
        float bias = b1[u];
        #pragma unroll
        for (int m = 0; m < 8; m++) acc[m] = bias;
        #pragma unroll 4
        for (int d = 0; d < DD; d++) {
            float w = W1[d*UU + u];
            float4 xa = *(const float4*)&xs_t[d][r0];
            float4 xb = *(const float4*)&xs_t[d][r0+4];
            acc[0] += xa.x*w; acc[1] += xa.y*w; acc[2] += xa.z*w; acc[3] += xa.w*w;
            acc[4] += xb.x*w; acc[5] += xb.y*w; acc[6] += xb.z*w; acc[7] += xb.w*w;
        }
        float4 o0 = make_float4(tshrink(acc[0]), tshrink(acc[1]), tshrink(acc[2]), tshrink(acc[3]));
        float4 o1 = make_float4(tshrink(acc[4]), tshrink(acc[5]), tshrink(acc[6]), tshrink(acc[7]));
        *(float4*)&h1_t[u][r0]   = o0;
        *(float4*)&h1_t[u][r0+4] = o1;
    }
    __syncthreads();

    {
        float acc[8];
        float bias = b2[u];
        #pragma unroll
        for (int m = 0; m < 8; m++) acc[m] = bias;
        #pragma unroll 4
        for (int d = 0; d < UU; d++) {
            float w = W2[d*UU + u];
            float4 xa = *(const float4*)&h1_t[d][r0];
            float4 xb = *(const float4*)&h1_t[d][r0+4];
            acc[0] += xa.x*w; acc[1] += xa.y*w; acc[2] += xa.z*w; acc[3] += xa.w*w;
            acc[4] += xb.x*w; acc[5] += xb.y*w; acc[6] += xb.z*w; acc[7] += xb.w*w;
        }
        float4 o0 = make_float4(tshrink(acc[0]), tshrink(acc[1]), tshrink(acc[2]), tshrink(acc[3]));
        float4 o1 = make_float4(tshrink(acc[4]), tshrink(acc[5]), tshrink(acc[6]), tshrink(acc[7]));
        *(float4*)&h2_t[u][r0]   = o0;
        *(float4*)&h2_t[u][r0+4] = o1;
    }
    __syncthreads();

    {
        int r = tid >> 3, s = tid & 7;
        float acc = 0.0f;
        #pragma unroll
        for (int k = 0; k < 8; k++) {
            int uu = s + 8*k;
            acc += h2_t[uu][r] * W3[uu];
        }
        acc += __shfl_xor_sync(0xffffffffu, acc, 1);
        acc += __shfl_xor_sync(0xffffffffu, acc, 2);
        acc += __shfl_xor_sync(0xffffffffu, acc, 4);
        if (s == 0) g_chi[row0 + r] = tshrink(acc + b3[0]);
    }
}

// ---------------------------------------------------------------------------
// Build A (B,N,N): 32x32 tile per block, write to output AND scratch
// ---------------------------------------------------------------------------
__global__ __launch_bounds__(256) void buildA_kernel(
    const float* __restrict__ pos,
    const int*   __restrict__ ntype,
    const float* __restrict__ hardness,
    const float* __restrict__ sigma,
    float* __restrict__ outA)
{
    __shared__ float pix[32], piy[32], piz[32];
    __shared__ float pjx[32], pjy[32], pjz[32];
    __shared__ float si[32], sj[32], hi[32];

    const int b  = blockIdx.z;
    const int it = blockIdx.y, jt = blockIdx.x;
    const int tid = threadIdx.x;
    const float kC = 14.399645351950548f;

    if (tid < 32) {
        int gi = it*32 + tid;
        const float* p = pos + ((size_t)b*NN + gi)*3;
        pix[tid]=p[0]; piy[tid]=p[1]; piz[tid]=p[2];
        int t = ntype[b*NN + gi];
        si[tid] = sigma[t]; hi[tid] = hardness[t];
    } else if (tid < 64) {
        int l = tid - 32;
        int gj = jt*32 + l;
        const float* p = pos + ((size_t)b*NN + gj)*3;
        pjx[l]=p[0]; pjy[l]=p[1]; pjz[l]=p[2];
        sj[l] = sigma[ntype[b*NN + gj]];
    }
    __syncthreads();

    float* Ab = outA + (size_t)b*NN*NN;
    float* Mb = g_M  + (size_t)b*NN*NN;

    for (int e = tid; e < 32*32; e += 256) {
        int li = e >> 5, lj = e & 31;
        int i = it*32 + li, j = jt*32 + lj;
        float dx = pix[li]-pjx[lj], dy = piy[li]-pjy[lj], dz = piz[li]-pjz[lj];
        float dist = sqrtf(dx*dx + dy*dy + dz*dz) + 1e-8f;
        float g2 = si[li]*si[li] + sj[lj]*sj[lj];
        float arg = dist * rsqrtf(2.0f * g2);
        float a = kC * erff(arg) / dist;
        if (i == j) {
            a += hi[li] + kC / (1.7724538509055159f * 1.4142135623730951f * si[li]);
        }
        size_t off = (size_t)i*NN + j;
        Ab[off] = a;
        Mb[off] = a;
    }
}

// ---------------------------------------------------------------------------
// Fused per-batch Cholesky factorization + triangular solves + Schur combine.
// One CTA per batch, 512 threads, whole panel held in smem across trsm+syrk.
// ---------------------------------------------------------------------------
extern __shared__ float sh[];

__global__ __launch_bounds__(512, 1) void factor_solve_kernel(
    const float* __restrict__ tq, float* __restrict__ outC)
{
    const int b = blockIdx.x, tid = threadIdx.x;  // 512
    float* Mb = g_M + (size_t)b*NN*NN;

    float* P  = sh;
    float* Sd = sh + OFF_S;    // [64][65] diag block
    float* Xi = sh + OFF_X;    // [64][65] invL
    float* Xt = sh + OFF_XT;   // [64][65] invL transposed
    float* Tt = sh + OFF_TT;   // [32][33]
    float* di = sh + OFF_DI;   // [64]

    // ======================= FACTORIZATION =======================
    for (int s = 0; s < NSTEPS; s++) {
        const int k0 = s*NB;
        const int R  = NSTEPS - 1 - s;

        // ---- load diagonal block
        for (int idx = tid; idx < NB*NB; idx += 512)
            Sd[(idx>>6)*65 + (idx&63)] = Mb[(size_t)(k0 + (idx>>6))*NN + k0 + (idx&63)];
        __syncthreads();

        // ---- LDL-style elimination, 1 barrier/iter, row-restricted sweep
        for (int j = 0; j < NB; j++) {
            float invd = 1.0f / Sd[j*65 + j];
            int cnt = (63 - j) * 64;
            for (int idx = tid; idx < cnt; idx += 512) {
                int i = j + 1 + (idx>>6), c = idx & 63;
                if (c > j && i >= c)
                    Sd[i*65 + c] -= Sd[i*65 + j] * (Sd[c*65 + j] * invd);
            }
            __syncthreads();
        }
        if (tid < NB) di[tid] = rsqrtf(Sd[tid*65 + tid]);
        __syncthreads();
        for (int idx = tid; idx < NB*NB; idx += 512) {
            int i = idx>>6, c = idx & 63;
            if (i >= c) Sd[i*65 + c] *= di[c];
        }
        __syncthreads();

        // write L11 back
        for (int idx = tid; idx < NB*NB; idx += 512)
            Mb[(size_t)(k0 + (idx>>6))*NN + k0 + (idx&63)] = Sd[(idx>>6)*65 + (idx&63)];

        // ---- invert L11 (block 2x2): two warp-local 32x32 inversions
        if (tid < 64) {
            int h = tid >> 5, j = tid & 31, base = h*32;
            for (int i = 0; i < 32; i++) {
                float acc = (i == j) ? 1.0f : 0.0f;
                for (int p = 0; p < i; p++)
                    acc -= Sd[(base+i)*65 + base+p] * Xi[(base+p)*65 + base+j];
                Xi[(base+i)*65 + base+j] = acc * di[base+i];
                __syncwarp();
            }
        }
        __syncthreads();
        for (int idx = tid; idx < 32*32; idx += 512) {
            int i = idx>>5, j = idx & 31;
            float acc = 0.0f;
            #pragma unroll 8
            for (int p = 0; p < 32; p++) acc += Sd[(32+i)*65 + p] * Xi[p*65 + j];
            Tt[i*33 + j] = acc;
            Xi[i*65 + 32 + j] = 0.0f;
        }
        __syncthreads();
        for (int idx = tid; idx < 32*32; idx += 512) {
            int i = idx>>5, j = idx & 31;
            float acc = 0.0f;
            #pragma unroll 8
            for (int p = 0; p < 32; p++) acc += Xi[(32+i)*65 + 32+p] * Tt[p*33 + j];
            Xi[(32+i)*65 + j] = -acc;
        }
        __syncthreads();

        // write g_Linv + build transposed copy Xt[k][j] = invL[j][k]
        {
            float* Xb = g_Linv + ((size_t)s*BB + b)*NB*NB;
            for (int idx = tid; idx < NB*NB; idx += 512) {
                int i = idx>>6, j = idx & 63;
                float v = Xi[i*65 + j];
                Xb[idx] = v;
                Xt[j*65 + i] = v;
            }
        }
        __syncthreads();

        if (R == 0) break;
        const int M2 = R*NB;

        // ---- load A21 panel transposed: P[k][i] = A[k0+64+i][k0+k]
        for (int idx = tid; idx < M2*NB; idx += 512) {
            int i = idx>>6, k = idx & 63;
            P[k*PSTRIDE + i] = Mb[(size_t)(k0 + NB + i)*NN + k0 + k];
        }
        __syncthreads();

        // ---- trsm: L21 = A21 * invL11^T, per 64x64 tile (2x4 microtile)
        {
            const int ty = tid >> 4, tx = tid & 15;
            for (int t = 0; t < R; t++) {
                const int r0 = t*64 + 2*ty;
                float acc[2][4] = {};
                #pragma unroll 4
                for (int k = 0; k < NB; k++) {
                    float a0 = P[k*PSTRIDE + r0];
                    float a1 = P[k*PSTRIDE + r0 + 1];
                    const float* xr = Xt + k*65 + 4*tx;
                    float x0 = xr[0], x1 = xr[1], x2 = xr[2], x3 = xr[3];
                    acc[0][0] += a0*x0; acc[0][1] += a0*x1; acc[0][2] += a0*x2; acc[0][3] += a0*x3;
                    acc[1][0] += a1*x0; acc[1][1] += a1*x1; acc[1][2] += a1*x2; acc[1][3] += a1*x3;
                }
                __syncthreads();
                #pragma unroll
                for (int u = 0; u < 2; u++) {
                    *(float4*)(Mb + (size_t)(k0 + NB + r0 + u)*NN + k0 + 4*tx) =
                        make_float4(acc[u][0], acc[u][1], acc[u][2], acc[u][3]);
                    P[(4*tx+0)*PSTRIDE + r0 + u] = acc[u][0];
                    P[(4*tx+1)*PSTRIDE + r0 + u] = acc[u][1];
                    P[(4*tx+2)*PSTRIDE + r0 + u] = acc[u][2];
                    P[(4*tx+3)*PSTRIDE + r0 + u] = acc[u][3];
                }
                __syncthreads();
            }
        }

        // ---- syrk: C -= L21 * L21^T, 8 tile-groups x (8x8 microtile, 64 thr)
        {
            const int grp = tid >> 6, lane = tid & 63;
            const int sy = lane >> 3, sx = lane & 7;
            const int T = R*(R+1)/2;
            for (int tt = grp; tt < T; tt += 8) {
                int ti = 0;
                while ((ti+1)*(ti+2)/2 <= tt) ti++;
                int tj = tt - ti*(ti+1)/2;

                float acc[8][8] = {};
                const int oi = ti*64 + 8*sy;
                const int oj = tj*64 + 8*sx;
                #pragma unroll 2
                for (int k = 0; k < NB; k++) {
                    const float* prow = P + k*PSTRIDE;
                    float av[8], bv[8];
                    #pragma unroll
                    for (int u = 0; u < 8; u++) av[u] = prow[oi + u];
                    #pragma unroll
                    for (int v = 0; v < 8; v++) bv[v] = prow[oj + v];
                    #pragma unroll
                    for (int u = 0; u < 8; u++)
                        #pragma unroll
                        for (int v = 0; v < 8; v++)
                            acc[u][v] += av[u] * bv[v];
                }
                #pragma unroll
                for (int u = 0; u < 8; u++) {
                    float* crow = Mb + (size_t)(k0 + NB + oi + u)*NN + k0 + NB + oj;
                    float4 c0 = *(float4*)(crow);
                    float4 c1 = *(float4*)(crow + 4);
                    c0.x -= acc[u][0]; c0.y -= acc[u][1]; c0.z -= acc[u][2]; c0.w -= acc[u][3];
                    c1.x -= acc[u][4]; c1.y -= acc[u][5]; c1.z -= acc[u][6]; c1.w -= acc[u][7];
                    *(float4*)(crow)     = c0;
                    *(float4*)(crow + 4) = c1;
                }
            }
        }
        __syncthreads();  // trailing matrix (global) visible before next step
    }

    // ======================= SOLVE =======================
    float* y1 = sh;           // [512]
    float* y2 = sh + 512;
    float* u1 = sh + 1024;    // [64]
    float* u2 = sh + 1088;
    float* rd = sh + 1152;    // [32]
    float* Bs = sh + OFF_X;   // [64][65] staging

    const int r = tid >> 3, q = tid & 7;

    y1[tid] = -g_chi[b*NN + tid];
    y2[tid] = 1.0f;
    __syncthreads();

    // ---- forward: L y = rhs
    for (int s = 0; s < NSTEPS; s++) {
        float a1 = 0.0f, a2 = 0.0f;
        for (int t = 0; t < s; t++) {
            const float* blk = Mb + (size_t)(s*NB + r)*NN + t*NB;
            #pragma unroll
            for (int k = q; k < NB; k += 8) {
                float w = blk[k];
                a1 += w * y1[t*NB + k];
                a2 += w * y2[t*NB + k];
            }
        }
        a1 += __shfl_xor_sync(0xffffffffu, a1, 1);
        a1 += __shfl_xor_sync(0xffffffffu, a1, 2);
        a1 += __shfl_xor_sync(0xffffffffu, a1, 4);
        a2 += __shfl_xor_sync(0xffffffffu, a2, 1);
        a2 += __shfl_xor_sync(0xffffffffu, a2, 2);
        a2 += __shfl_xor_sync(0xffffffffu, a2, 4);
        if (q == 0) { u1[r] = y1[s*NB + r] - a1; u2[r] = y2[s*NB + r] - a2; }
        __syncthreads();

        const float* Xb = g_Linv + ((size_t)s*BB + b)*NB*NB;
        float z1 = 0.0f, z2 = 0.0f;
        #pragma unroll
        for (int k = q; k < NB; k += 8) {
            float w = Xb[r*NB + k];
            z1 += w * u1[k];
            z2 += w * u2[k];
        }
        z1 += __shfl_xor_sync(0xffffffffu, z1, 1);
        z1 += __shfl_xor_sync(0xffffffffu, z1, 2);
        z1 += __shfl_xor_sync(0xffffffffu, z1, 4);
        z2 += __shfl_xor_sync(0xffffffffu, z2, 1);
        z2 += __shfl_xor_sync(0xffffffffu, z2, 2);
        z2 += __shfl_xor_sync(0xffffffffu, z2, 4);
        if (q == 0) { y1[s*NB + r] = z1; y2[s*NB + r] = z2; }
        __syncthreads();
    }

    // ---- backward: L^T x = y  (stage transposed blocks in smem)
    for (int s = NSTEPS - 1; s >= 0; s--) {
        float a1 = 0.0f, a2 = 0.0f;
        for (int t = s + 1; t < NSTEPS; t++) {
            for (int idx = tid; idx < NB*NB; idx += 512) {
                int k = idx>>6, c = idx & 63;
                Bs[k*65 + c] = Mb[(size_t)(t*NB + k)*NN + s*NB + c];
            }
            __syncthreads();
            #pragma unroll
            for (int k = q; k < NB; k += 8) {
                float w = Bs[k*65 + r];
                a1 += w * y1[t*NB + k];
                a2 += w * y2[t*NB + k];
            }
            __syncthreads();
        }
        a1 += __shfl_xor_sync(0xffffffffu, a1, 1);
        a1 += __shfl_xor_sync(0xffffffffu, a1, 2);
        a1 += __shfl_xor_sync(0xffffffffu, a1, 4);
        a2 += __shfl_xor_sync(0xffffffffu, a2, 1);
        a2 += __shfl_xor_sync(0xffffffffu, a2, 2);
        a2 += __shfl_xor_sync(0xffffffffu, a2, 4);
        if (q == 0) { u1[r] = y1[s*NB + r] - a1; u2[r] = y2[s*NB + r] - a2; }
        __syncthreads();

        // stage invL block (coalesced), apply transposed
        {
            const float* Xb = g_Linv + ((size_t)s*BB + b)*NB*NB;
            for (int idx = tid; idx < NB*NB; idx += 512)
                Bs[(idx>>6)*65 + (idx&63)] = Xb[idx];
        }
        __syncthreads();
        float z1 = 0.0f, z2 = 0.0f;
        #pragma unroll
        for (int k = q; k < NB; k += 8) {
            float w = Bs[k*65 + r];   // invL[k][r] = (invL^T)[r][k]
            z1 += w * u1[k];
            z2 += w * u2[k];
        }
        z1 += __shfl_xor_sync(0xffffffffu, z1, 1);
        z1 += __shfl_xor_sync(0xffffffffu, z1, 2);
        z1 += __shfl_xor_sync(0xffffffffu, z1, 4);
        z2 += __shfl_xor_sync(0xffffffffu, z2, 1);
        z2 += __shfl_xor_sync(0xffffffffu, z2, 2);
        z2 += __shfl_xor_sync(0xffffffffu, z2, 4);
        if (q == 0) { y1[s*NB + r] = z1; y2[s*NB + r] = z2; }
        __syncthreads();
    }

    // ---- Schur combine: mu = (1^T x1 - Q) / (1^T x2);  q = x1 - mu*x2
    float s1 = y1[tid], s2 = y2[tid];
    #pragma unroll
    for (int o = 16; o > 0; o >>= 1) {
        s1 += __shfl_xor_sync(0xffffffffu, s1, o);
        s2 += __shfl_xor_sync(0xffffffffu, s2, o);
    }
    if ((tid & 31) == 0) { rd[tid >> 5] = s1; rd[16 + (tid >> 5)] = s2; }
    __syncthreads();
    if (tid == 0) {
        float S1 = 0.0f, S2 = 0.0f;
        for (int w = 0; w < 16; w++) { S1 += rd[w]; S2 += rd[16 + w]; }
        rd[0] = (S1 - tq[b]) / S2;
    }
    __syncthreads();
    float mu = rd[0];
    outC[b*NN + tid] = y1[tid] - mu * y2[tid];
}

// ---------------------------------------------------------------------------
extern "C" void kernel_launch(void* const* d_in, const int* in_sizes, int n_in,
                              void* d_out, int out_size)
{
    const float* pos   = (const float*)d_in[0];
    const float* nf    = (const float*)d_in[1];
    const int*   ntype = (const int*)  d_in[2];
    const float* tq    = (const float*)d_in[3];
    const float* hard  = (const float*)d_in[4];
    const float* sig   = (const float*)d_in[5];
    const float* W1    = (const float*)d_in[6];
    const float* b1    = (const float*)d_in[7];
    const float* W2    = (const float*)d_in[8];
    const float* b2    = (const float*)d_in[9];
    const float* W3    = (const float*)d_in[10];
    const float* b3    = (const float*)d_in[11];

    float* outC = (float*)d_out;          // charges (B,N)
    float* outA = (float*)d_out + BB*NN;  // A (B,N,N)

    static int smem_set = 0;
    if (!smem_set) {
        cudaFuncSetAttribute(factor_solve_kernel,
                             cudaFuncAttributeMaxDynamicSharedMemorySize, SMEM_BYTES);
        smem_set = 1;
    }

    chi_kernel<<<(BB*NN)/32, 256>>>(nf, W1, b1, W2, b2, W3, b3);
    buildA_kernel<<<dim3(NN/32, NN/32, BB), 256>>>(pos, ntype, hard, sig, outA);
    factor_solve_kernel<<<BB, 512, SMEM_BYTES>>>(tq, outC);
}

// round 8
// speedup vs baseline: 2.6594x; 1.1378x over previous
#include <cuda_runtime.h>
#include <math.h>

#define BB 64
#define NN 512
#define DD 128
#define UU 64
#define NB 64
#define NSTEPS (NN/NB)

#define PSTRIDE 449              // odd -> conflict-free transposed panel stores
#define OFF_S   28736            // 64*449
#define OFF_X   (OFF_S + 64*65)
#define OFF_XT  (OFF_X + 64*65)
#define OFF_TT  (OFF_XT + 64*65)
#define OFF_DI  (OFF_TT + 32*33)
#define SMEM_FLOATS (OFF_DI + 64)
#define SMEM_BYTES (SMEM_FLOATS*4)   // 169,344 B

// Scratch (allocation-free rule: __device__ globals)
__device__ float g_M[BB*NN*NN];              // Cholesky workspace (copy of A)
__device__ float g_chi[BB*NN];
__device__ float g_Linv[NSTEPS*BB*NB*NB];    // inv of each diagonal block L11
__device__ float g_xv[BB*NN];                // x2 handoff (rank1 -> rank0)

__device__ __forceinline__ float tshrink(float x) { return x - tanhf(x); }

#define CLUSTER_SYNC() do { \
    asm volatile("barrier.cluster.arrive.aligned;" ::: "memory"); \
    asm volatile("barrier.cluster.wait.aligned;" ::: "memory"); \
} while(0)

// ---------------------------------------------------------------------------
// chi = MLP(node_feats): 32 rows per block, 256 threads.
// Thread = (u-pair, row-group of 4): per d-iter 1 LDG.64 + 1 LDS.128 -> 8 FFMA.
// Store mapping keeps each 8-lane STS.128 phase within one smem row (no bank
// conflicts).
// ---------------------------------------------------------------------------
__global__ __launch_bounds__(256) void chi_kernel(
    const float* __restrict__ nf,
    const float* __restrict__ W1, const float* __restrict__ b1,
    const float* __restrict__ W2, const float* __restrict__ b2,
    const float* __restrict__ W3, const float* __restrict__ b3)
{
    __shared__ float xs_t[DD][36];
    __shared__ float h1_t[UU][36];
    __shared__ float h2_t[UU][36];
    const int row0 = blockIdx.x * 32;
    const int tid  = threadIdx.x;
    const int pid = tid >> 3;     // 0..31 -> u0 = 2*pid
    const int rg  = tid & 7;      // -> r0 = 4*rg
    const int u0 = 2*pid, r0 = 4*rg;

    #pragma unroll
    for (int t = 0; t < 4; t++) {
        int f = tid + 256*t;
        int r = f >> 5, c4 = f & 31;
        float4 v = *(const float4*)(nf + (size_t)(row0 + r)*DD + c4*4);
        xs_t[c4*4+0][r] = v.x;
        xs_t[c4*4+1][r] = v.y;
        xs_t[c4*4+2][r] = v.z;
        xs_t[c4*4+3][r] = v.w;
    }
    __syncthreads();

    // layer 1
    {
        float2 bb = *(const float2*)&b1[u0];
        float acc0[4] = {bb.x, bb.x, bb.x, bb.x};
        float acc1[4] = {bb.y, bb.y, bb.y, bb.y};
        #pragma unroll 4
        for (int d = 0; d < DD; d++) {
            float2 w = *(const float2*)&W1[d*UU + u0];
            float4 xa = *(const float4*)&xs_t[d][r0];
            acc0[0] += xa.x*w.x; acc0[1] += xa.y*w.x; acc0[2] += xa.z*w.x; acc0[3] += xa.w*w.x;
            acc1[0] += xa.x*w.y; acc1[1] += xa.y*w.y; acc1[2] += xa.z*w.y; acc1[3] += xa.w*w.y;
        }
        *(float4*)&h1_t[u0][r0]   = make_float4(tshrink(acc0[0]), tshrink(acc0[1]), tshrink(acc0[2]), tshrink(acc0[3]));
        *(float4*)&h1_t[u0+1][r0] = make_float4(tshrink(acc1[0]), tshrink(acc1[1]), tshrink(acc1[2]), tshrink(acc1[3]));
    }
    __syncthreads();

    // layer 2
    {
        float2 bb = *(const float2*)&b2[u0];
        float acc0[4] = {bb.x, bb.x, bb.x, bb.x};
        float acc1[4] = {bb.y, bb.y, bb.y, bb.y};
        #pragma unroll 4
        for (int d = 0; d < UU; d++) {
            float2 w = *(const float2*)&W2[d*UU + u0];
            float4 xa = *(const float4*)&h1_t[d][r0];
            acc0[0] += xa.x*w.x; acc0[1] += xa.y*w.x; acc0[2] += xa.z*w.x; acc0[3] += xa.w*w.x;
            acc1[0] += xa.x*w.y; acc1[1] += xa.y*w.y; acc1[2] += xa.z*w.y; acc1[3] += xa.w*w.y;
        }
        *(float4*)&h2_t[u0][r0]   = make_float4(tshrink(acc0[0]), tshrink(acc0[1]), tshrink(acc0[2]), tshrink(acc0[3]));
        *(float4*)&h2_t[u0+1][r0] = make_float4(tshrink(acc1[0]), tshrink(acc1[1]), tshrink(acc1[2]), tshrink(acc1[3]));
    }
    __syncthreads();

    // layer 3: chi[r] = tshrink(h2[r] . W3 + b3); 8 threads per row
    {
        int r = tid >> 3, s = tid & 7;
        float acc = 0.0f;
        #pragma unroll
        for (int k = 0; k < 8; k++) {
            int uu = s + 8*k;
            acc += h2_t[uu][r] * W3[uu];
        }
        acc += __shfl_xor_sync(0xffffffffu, acc, 1);
        acc += __shfl_xor_sync(0xffffffffu, acc, 2);
        acc += __shfl_xor_sync(0xffffffffu, acc, 4);
        if (s == 0) g_chi[row0 + r] = tshrink(acc + b3[0]);
    }
}

// ---------------------------------------------------------------------------
// Build A (B,N,N): 32x32 tile per block, write to output AND scratch
// ---------------------------------------------------------------------------
__global__ __launch_bounds__(256) void buildA_kernel(
    const float* __restrict__ pos,
    const int*   __restrict__ ntype,
    const float* __restrict__ hardness,
    const float* __restrict__ sigma,
    float* __restrict__ outA)
{
    __shared__ float pix[32], piy[32], piz[32];
    __shared__ float pjx[32], pjy[32], pjz[32];
    __shared__ float si[32], sj[32], hi[32];

    const int b  = blockIdx.z;
    const int it = blockIdx.y, jt = blockIdx.x;
    const int tid = threadIdx.x;
    const float kC = 14.399645351950548f;

    if (tid < 32) {
        int gi = it*32 + tid;
        const float* p = pos + ((size_t)b*NN + gi)*3;
        pix[tid]=p[0]; piy[tid]=p[1]; piz[tid]=p[2];
        int t = ntype[b*NN + gi];
        si[tid] = sigma[t]; hi[tid] = hardness[t];
    } else if (tid < 64) {
        int l = tid - 32;
        int gj = jt*32 + l;
        const float* p = pos + ((size_t)b*NN + gj)*3;
        pjx[l]=p[0]; pjy[l]=p[1]; pjz[l]=p[2];
        sj[l] = sigma[ntype[b*NN + gj]];
    }
    __syncthreads();

    float* Ab = outA + (size_t)b*NN*NN;
    float* Mb = g_M  + (size_t)b*NN*NN;

    for (int e = tid; e < 32*32; e += 256) {
        int li = e >> 5, lj = e & 31;
        int i = it*32 + li, j = jt*32 + lj;
        float dx = pix[li]-pjx[lj], dy = piy[li]-pjy[lj], dz = piz[li]-pjz[lj];
        float dist = sqrtf(dx*dx + dy*dy + dz*dz) + 1e-8f;
        float g2 = si[li]*si[li] + sj[lj]*sj[lj];
        float arg = dist * rsqrtf(2.0f * g2);
        float a = kC * erff(arg) / dist;
        if (i == j) {
            a += hi[li] + kC / (1.7724538509055159f * 1.4142135623730951f * si[li]);
        }
        size_t off = (size_t)i*NN + j;
        Ab[off] = a;
        Mb[off] = a;
    }
}

// ---------------------------------------------------------------------------
// Fused per-batch Cholesky + triangular solves + Schur combine.
// One 2-CTA CLUSTER per batch: potrf redundant, trsm/syrk tile-split by rank,
// solve split by RHS (rank0: -chi, rank1: ones).
// ---------------------------------------------------------------------------
extern __shared__ float sh[];

__global__ __launch_bounds__(512, 1) __cluster_dims__(2, 1, 1)
void factor_solve_kernel(const float* __restrict__ tq, float* __restrict__ outC)
{
    const int b    = blockIdx.x >> 1;
    const int rank = blockIdx.x & 1;
    const int tid  = threadIdx.x;  // 512
    float* Mb = g_M + (size_t)b*NN*NN;

    float* P  = sh;
    float* Sd = sh + OFF_S;    // [64][65] diag block
    float* Xi = sh + OFF_X;    // [64][65] invL
    float* Xt = sh + OFF_XT;   // [64][65] invL transposed
    float* Tt = sh + OFF_TT;   // [32][33]
    float* di = sh + OFF_DI;   // [64]

    // ======================= FACTORIZATION =======================
    for (int s = 0; s < NSTEPS; s++) {
        const int k0 = s*NB;
        const int R  = NSTEPS - 1 - s;

        // ---- load diagonal block (both CTAs, identical)
        for (int idx = tid; idx < NB*NB; idx += 512)
            Sd[(idx>>6)*65 + (idx&63)] = Mb[(size_t)(k0 + (idx>>6))*NN + k0 + (idx&63)];
        __syncthreads();

        // ---- LDL-style elimination, 1 barrier/iter (redundant in both CTAs)
        for (int j = 0; j < NB; j++) {
            float invd = 1.0f / Sd[j*65 + j];
            int cnt = (63 - j) * 64;
            for (int idx = tid; idx < cnt; idx += 512) {
                int i = j + 1 + (idx>>6), c = idx & 63;
                if (c > j && i >= c)
                    Sd[i*65 + c] -= Sd[i*65 + j] * (Sd[c*65 + j] * invd);
            }
            __syncthreads();
        }
        if (tid < NB) di[tid] = rsqrtf(Sd[tid*65 + tid]);
        __syncthreads();
        for (int idx = tid; idx < NB*NB; idx += 512) {
            int i = idx>>6, c = idx & 63;
            if (i >= c) Sd[i*65 + c] *= di[c];
        }
        __syncthreads();

        // ---- invert L11 (block 2x2): two warp-local 32x32 inversions
        if (tid < 64) {
            int h = tid >> 5, j = tid & 31, base = h*32;
            for (int i = 0; i < 32; i++) {
                float acc = (i == j) ? 1.0f : 0.0f;
                for (int p = 0; p < i; p++)
                    acc -= Sd[(base+i)*65 + base+p] * Xi[(base+p)*65 + base+j];
                Xi[(base+i)*65 + base+j] = acc * di[base+i];
                __syncwarp();
            }
        }
        __syncthreads();
        for (int idx = tid; idx < 32*32; idx += 512) {
            int i = idx>>5, j = idx & 31;
            float acc = 0.0f;
            #pragma unroll 8
            for (int p = 0; p < 32; p++) acc += Sd[(32+i)*65 + p] * Xi[p*65 + j];
            Tt[i*33 + j] = acc;
            Xi[i*65 + 32 + j] = 0.0f;
        }
        __syncthreads();
        for (int idx = tid; idx < 32*32; idx += 512) {
            int i = idx>>5, j = idx & 31;
            float acc = 0.0f;
            #pragma unroll 8
            for (int p = 0; p < 32; p++) acc += Xi[(32+i)*65 + 32+p] * Tt[p*33 + j];
            Xi[(32+i)*65 + j] = -acc;
        }
        __syncthreads();

        // write g_Linv (both CTAs write identical values - benign) + Xt
        {
            float* Xb = g_Linv + ((size_t)s*BB + b)*NB*NB;
            for (int idx = tid; idx < NB*NB; idx += 512) {
                int i = idx>>6, j = idx & 63;
                float v = Xi[i*65 + j];
                Xb[idx] = v;
                Xt[j*65 + i] = v;
            }
        }
        __syncthreads();

        if (R == 0) break;

        // ---- load OWN A21 tiles transposed: P[k][i] = A[k0+64+i][k0+k]
        for (int t = rank; t < R; t += 2)
            for (int idx = tid; idx < NB*NB; idx += 512) {
                int i = t*64 + (idx>>6), k = idx & 63;
                P[k*PSTRIDE + i] = Mb[(size_t)(k0 + NB + i)*NN + k0 + k];
            }
        __syncthreads();

        // ---- trsm on own tiles: L21 = A21 * invL11^T  (2x4 microtile)
        {
            const int ty = tid >> 4, tx = tid & 15;
            for (int t = rank; t < R; t += 2) {
                const int r0 = t*64 + 2*ty;
                float acc[2][4] = {};
                #pragma unroll 4
                for (int k = 0; k < NB; k++) {
                    float a0 = P[k*PSTRIDE + r0];
                    float a1 = P[k*PSTRIDE + r0 + 1];
                    const float* xr = Xt + k*65 + 4*tx;
                    float x0 = xr[0], x1 = xr[1], x2 = xr[2], x3 = xr[3];
                    acc[0][0] += a0*x0; acc[0][1] += a0*x1; acc[0][2] += a0*x2; acc[0][3] += a0*x3;
                    acc[1][0] += a1*x0; acc[1][1] += a1*x1; acc[1][2] += a1*x2; acc[1][3] += a1*x3;
                }
                __syncthreads();
                #pragma unroll
                for (int u = 0; u < 2; u++) {
                    *(float4*)(Mb + (size_t)(k0 + NB + r0 + u)*NN + k0 + 4*tx) =
                        make_float4(acc[u][0], acc[u][1], acc[u][2], acc[u][3]);
                    P[(4*tx+0)*PSTRIDE + r0 + u] = acc[u][0];
                    P[(4*tx+1)*PSTRIDE + r0 + u] = acc[u][1];
                    P[(4*tx+2)*PSTRIDE + r0 + u] = acc[u][2];
                    P[(4*tx+3)*PSTRIDE + r0 + u] = acc[u][3];
                }
                __syncthreads();
            }
        }

        __threadfence();
        CLUSTER_SYNC();

        // ---- fetch peer CTA's L21 tiles from global into P
        for (int t = rank ^ 1; t < R; t += 2)
            for (int idx = tid; idx < NB*NB; idx += 512) {
                int i = t*64 + (idx>>6), k = idx & 63;
                P[k*PSTRIDE + i] = Mb[(size_t)(k0 + NB + i)*NN + k0 + k];
            }
        __syncthreads();

        // ---- syrk: C -= L21 * L21^T; 16 tile-groups across the cluster
        {
            const int grp = (rank << 3) | (tid >> 6);   // 0..15
            const int lane = tid & 63;
            const int sy = lane >> 3, sx = lane & 7;
            const int T = R*(R+1)/2;
            for (int tt = grp; tt < T; tt += 16) {
                int ti = 0;
                while ((ti+1)*(ti+2)/2 <= tt) ti++;
                int tj = tt - ti*(ti+1)/2;

                float acc[8][8] = {};
                const int oi = ti*64 + 8*sy;
                const int oj = tj*64 + 8*sx;
                #pragma unroll 2
                for (int k = 0; k < NB; k++) {
                    const float* prow = P + k*PSTRIDE;
                    float av[8], bv[8];
                    #pragma unroll
                    for (int u = 0; u < 8; u++) av[u] = prow[oi + u];
                    #pragma unroll
                    for (int v = 0; v < 8; v++) bv[v] = prow[oj + v];
                    #pragma unroll
                    for (int u = 0; u < 8; u++)
                        #pragma unroll
                        for (int v = 0; v < 8; v++)
                            acc[u][v] += av[u] * bv[v];
                }
                #pragma unroll
                for (int u = 0; u < 8; u++) {
                    float* crow = Mb + (size_t)(k0 + NB + oi + u)*NN + k0 + NB + oj;
                    float4 c0 = *(float4*)(crow);
                    float4 c1 = *(float4*)(crow + 4);
                    c0.x -= acc[u][0]; c0.y -= acc[u][1]; c0.z -= acc[u][2]; c0.w -= acc[u][3];
                    c1.x -= acc[u][4]; c1.y -= acc[u][5]; c1.z -= acc[u][6]; c1.w -= acc[u][7];
                    *(float4*)(crow)     = c0;
                    *(float4*)(crow + 4) = c1;
                }
            }
        }

        __threadfence();
        CLUSTER_SYNC();   // trailing matrix visible to both CTAs before next step
    }

    // ======================= SOLVE (1 RHS per CTA) =======================
    float* y  = sh;           // [512]
    float* u  = sh + 512;     // [64]
    float* rd = sh + 576;     // [32]
    float* Bs = sh + OFF_X;   // [64][65] staging

    const int r = tid >> 3, q = tid & 7;

    y[tid] = rank ? 1.0f : -g_chi[b*NN + tid];
    __syncthreads();

    // ---- forward: L y = rhs
    for (int s = 0; s < NSTEPS; s++) {
        float a = 0.0f;
        for (int t = 0; t < s; t++) {
            const float* blk = Mb + (size_t)(s*NB + r)*NN + t*NB;
            #pragma unroll
            for (int k = q; k < NB; k += 8)
                a += blk[k] * y[t*NB + k];
        }
        a += __shfl_xor_sync(0xffffffffu, a, 1);
        a += __shfl_xor_sync(0xffffffffu, a, 2);
        a += __shfl_xor_sync(0xffffffffu, a, 4);
        if (q == 0) u[r] = y[s*NB + r] - a;
        __syncthreads();

        const float* Xb = g_Linv + ((size_t)s*BB + b)*NB*NB;
        float z = 0.0f;
        #pragma unroll
        for (int k = q; k < NB; k += 8)
            z += Xb[r*NB + k] * u[k];
        z += __shfl_xor_sync(0xffffffffu, z, 1);
        z += __shfl_xor_sync(0xffffffffu, z, 2);
        z += __shfl_xor_sync(0xffffffffu, z, 4);
        if (q == 0) y[s*NB + r] = z;
        __syncthreads();
    }

    // ---- backward: L^T x = y
    for (int s = NSTEPS - 1; s >= 0; s--) {
        float a = 0.0f;
        for (int t = s + 1; t < NSTEPS; t++) {
            for (int idx = tid; idx < NB*NB; idx += 512) {
                int k = idx>>6, c = idx & 63;
                Bs[k*65 + c] = Mb[(size_t)(t*NB + k)*NN + s*NB + c];
            }
            __syncthreads();
            #pragma unroll
            for (int k = q; k < NB; k += 8)
                a += Bs[k*65 + r] * y[t*NB + k];
            __syncthreads();
        }
        a += __shfl_xor_sync(0xffffffffu, a, 1);
        a += __shfl_xor_sync(0xffffffffu, a, 2);
        a += __shfl_xor_sync(0xffffffffu, a, 4);
        if (q == 0) u[r] = y[s*NB + r] - a;
        __syncthreads();

        {
            const float* Xb = g_Linv + ((size_t)s*BB + b)*NB*NB;
            for (int idx = tid; idx < NB*NB; idx += 512)
                Bs[(idx>>6)*65 + (idx&63)] = Xb[idx];
        }
        __syncthreads();
        float z = 0.0f;
        #pragma unroll
        for (int k = q; k < NB; k += 8)
            z += Bs[k*65 + r] * u[k];   // invL[k][r] = (invL^T)[r][k]
        z += __shfl_xor_sync(0xffffffffu, z, 1);
        z += __shfl_xor_sync(0xffffffffu, z, 2);
        z += __shfl_xor_sync(0xffffffffu, z, 4);
        if (q == 0) y[s*NB + r] = z;
        __syncthreads();
    }

    // ---- handoff x2 and combine on rank 0
    if (rank == 1) g_xv[b*NN + tid] = y[tid];
    __threadfence();
    CLUSTER_SYNC();

    if (rank == 0) {
        float x2 = g_xv[b*NN + tid];
        float s1 = y[tid], s2 = x2;
        #pragma unroll
        for (int o = 16; o > 0; o >>= 1) {
            s1 += __shfl_xor_sync(0xffffffffu, s1, o);
            s2 += __shfl_xor_sync(0xffffffffu, s2, o);
        }
        if ((tid & 31) == 0) { rd[tid >> 5] = s1; rd[16 + (tid >> 5)] = s2; }
        __syncthreads();
        if (tid == 0) {
            float S1 = 0.0f, S2 = 0.0f;
            for (int w = 0; w < 16; w++) { S1 += rd[w]; S2 += rd[16 + w]; }
            rd[0] = (S1 - tq[b]) / S2;
        }
        __syncthreads();
        float mu = rd[0];
        outC[b*NN + tid] = y[tid] - mu * x2;
    }
}

// ---------------------------------------------------------------------------
extern "C" void kernel_launch(void* const* d_in, const int* in_sizes, int n_in,
                              void* d_out, int out_size)
{
    const float* pos   = (const float*)d_in[0];
    const float* nf    = (const float*)d_in[1];
    const int*   ntype = (const int*)  d_in[2];
    const float* tq    = (const float*)d_in[3];
    const float* hard  = (const float*)d_in[4];
    const float* sig   = (const float*)d_in[5];
    const float* W1    = (const float*)d_in[6];
    const float* b1    = (const float*)d_in[7];
    const float* W2    = (const float*)d_in[8];
    const float* b2    = (const float*)d_in[9];
    const float* W3    = (const float*)d_in[10];
    const float* b3    = (const float*)d_in[11];

    float* outC = (float*)d_out;          // charges (B,N)
    float* outA = (float*)d_out + BB*NN;  // A (B,N,N)

    static int smem_set = 0;
    if (!smem_set) {
        cudaFuncSetAttribute(factor_solve_kernel,
                             cudaFuncAttributeMaxDynamicSharedMemorySize, SMEM_BYTES);
        smem_set = 1;
    }

    chi_kernel<<<(BB*NN)/32, 256>>>(nf, W1, b1, W2, b2, W3, b3);
    buildA_kernel<<<dim3(NN/32, NN/32, BB), 256>>>(pos, ntype, hard, sig, outA);
    factor_solve_kernel<<<2*BB, 512, SMEM_BYTES>>>(tq, outC);
}